// round 6
// baseline (speedup 1.0000x reference)
#include <cuda_runtime.h>
#include <math.h>

#define Bn 8
#define Cn 64
#define HW 65536
#define Sn 2048
#define OUTC 16

#define F_INV_TAU   14.2857142857142857f          /* 1/0.07 */
#define F_SCALE     20.6096954f                   /* log2(e)/0.07 */
#define F_LN2       0.69314718056f

// f32x2 packed helpers ------------------------------------------------------
typedef unsigned long long ull;
__device__ __forceinline__ ull pack2(float lo, float hi) {
    ull r;
    asm("mov.b64 %0, {%1, %2};" : "=l"(r) : "r"(__float_as_uint(lo)), "r"(__float_as_uint(hi)));
    return r;
}
__device__ __forceinline__ void unpack2(ull v, float& lo, float& hi) {
    unsigned a, b;
    asm("mov.b64 {%0, %1}, %2;" : "=r"(a), "=r"(b) : "l"(v));
    lo = __uint_as_float(a); hi = __uint_as_float(b);
}
#define FMA2(d, a, b) asm("fma.rn.f32x2 %0, %1, %2, %3;" : "=l"(d) : "l"(a), "l"(b), "l"(d))
#define ADD2(d, a)    asm("add.rn.f32x2 %0, %1, %2;"     : "=l"(d) : "l"(a), "l"(d))
#define MUL2(d, a, b) asm("mul.rn.f32x2 %0, %1, %2;"     : "=l"(d) : "l"(a), "l"(b))
__device__ __forceinline__ float ex2f(float x) {
    float y; asm("ex2.approx.f32 %0, %1;" : "=f"(y) : "f"(x)); return y;
}
__device__ __forceinline__ float lg2f(float x) {
    float y; asm("lg2.approx.f32 %0, %1;" : "=f"(y) : "f"(x)); return y;
}

// Scratch
__device__ float g_diff[2 * Bn * Cn * Sn];      // 8 MB
__device__ float g_fq[Bn * Sn * OUTC];
__device__ float g_fk[Bn * Sn * OUTC];

// ---------------------------------------------------------------------------
// Kernel A: gather + diff (+ zero the output scalar from block 0).
// grid = 2*B*C = 1024 blocks, 256 threads.
// ---------------------------------------------------------------------------
__global__ void gather_diff_kernel(const float* __restrict__ fq,
                                   const float* __restrict__ fk,
                                   const int*   __restrict__ c_ids,
                                   const int*   __restrict__ n_ids,
                                   float* __restrict__ out) {
    if (blockIdx.x == 0 && threadIdx.x == 0) out[0] = 0.0f;

    int gid = blockIdx.x;
    int map = gid >> 9;
    int bc  = gid & 511;
    int b   = bc >> 6;
    int c   = bc & 63;

    const float* feat = (map ? fk : fq) + ((size_t)b * Cn + c) * HW;
    float* dst = g_diff + ((size_t)(map * Bn + b) * Cn + c) * Sn;

    int j = threadIdx.x;
    float fc = __ldg(&feat[c_ids[j]]);

#pragma unroll
    for (int off = 0; off < 8; off++) {
        int s = off * 256 + j;
        dst[s] = fc - __ldg(&feat[n_ids[s]]);
    }
}

// ---------------------------------------------------------------------------
// Kernel B: MLP + L2-normalize (f32x2).  grid = 256, 128 threads,
// each thread owns one row entirely.
// ---------------------------------------------------------------------------
#define XPAD 68
__global__ __launch_bounds__(128) void mlp_kernel(const float* __restrict__ W0,
                                                  const float* __restrict__ b0,
                                                  const float* __restrict__ W1,
                                                  const float* __restrict__ b1) {
    extern __shared__ float smem[];
    float* sx  = smem;                       // 128*68
    float* sW0 = sx + 128 * XPAD;            // 64*64  (transposed: [t][c])
    float* sW1 = sW0 + 64 * 64;              // 64*16
    float* sb0 = sW1 + 64 * 16;              // 64
    float* sb1 = sb0 + 64;                   // 16

    int mb = blockIdx.x >> 4;
    int s0 = (blockIdx.x & 15) * 128;
    int tid = threadIdx.x;

    const float* src = g_diff + (size_t)mb * Cn * Sn;

    for (int i = tid; i < 4096; i += 128) {
        int c = i >> 6, t = i & 63;
        sW0[t * 64 + c] = __ldg(&W0[i]);
    }
    for (int i = tid; i < 1024; i += 128) sW1[i] = __ldg(&W1[i]);
    if (tid < 64) sb0[tid] = __ldg(&b0[tid]);
    if (tid < 16) sb1[tid] = __ldg(&b1[tid]);

    for (int i = tid; i < 64 * 128; i += 128) {
        int c = i >> 7, s = i & 127;
        sx[s * XPAD + c] = src[(size_t)c * Sn + s0 + s];
    }
    __syncthreads();

    ull x2[32];
#pragma unroll
    for (int i = 0; i < 16; i++) {
        float4 v = *reinterpret_cast<float4*>(&sx[tid * XPAD + i * 4]);
        x2[2 * i + 0] = pack2(v.x, v.y);
        x2[2 * i + 1] = pack2(v.z, v.w);
    }

    ull o2[8];
#pragma unroll
    for (int i = 0; i < 8; i++) o2[i] = pack2(sb1[2 * i], sb1[2 * i + 1]);

#pragma unroll 4
    for (int t = 0; t < 64; t++) {
        const ull* w2 = reinterpret_cast<const ull*>(&sW0[t * 64]);
        ull a0 = 0, a1 = 0, a2 = 0, a3 = 0;
#pragma unroll
        for (int i = 0; i < 8; i++) {
            FMA2(a0, x2[i +  0], w2[i +  0]);
            FMA2(a1, x2[i +  8], w2[i +  8]);
            FMA2(a2, x2[i + 16], w2[i + 16]);
            FMA2(a3, x2[i + 24], w2[i + 24]);
        }
        ADD2(a0, a1); ADD2(a2, a3); ADD2(a0, a2);
        float lo, hi; unpack2(a0, lo, hi);
        float h = fmaxf(lo + hi + sb0[t], 0.0f);
        ull h2 = pack2(h, h);
        const ull* w1 = reinterpret_cast<const ull*>(&sW1[t * 16]);
#pragma unroll
        for (int i = 0; i < 8; i++) FMA2(o2[i], h2, w1[i]);
    }

    float o[16];
#pragma unroll
    for (int i = 0; i < 8; i++) unpack2(o2[i], o[2 * i], o[2 * i + 1]);

    float sq = 0.f;
#pragma unroll
    for (int i = 0; i < 16; i++) sq = fmaf(o[i], o[i], sq);
    float inv = 1.0f / (sqrtf(sq) + 1e-7f);

    float* dst = (mb < Bn ? g_fq + (size_t)mb * Sn * OUTC
                          : g_fk + (size_t)(mb - Bn) * Sn * OUTC)
                 + (size_t)(s0 + tid) * OUTC;
#pragma unroll
    for (int oo = 0; oo < 4; oo++) {
        float4 v = make_float4(o[oo * 4 + 0] * inv, o[oo * 4 + 1] * inv,
                               o[oo * 4 + 2] * inv, o[oo * 4 + 3] * inv);
        *reinterpret_cast<float4*>(&dst[oo * 4]) = v;
    }
}

// ---------------------------------------------------------------------------
// Kernel C: PatchNCE loss (v5 — channel-pair f32x2, fixed diagonal constant).
//   x_st = q'.k_t - SCALE  (q' = q*SCALE, SCALE = log2e/tau)
//   loss_row = ln2 * ( log2( sum_t exp2(x_st) ) - x_ss )     [exact identity]
//   512 threads = 16 warps x 4 rows = 64 rows/block; grid = B*32.
// ---------------------------------------------------------------------------
__global__ __launch_bounds__(512, 1) void loss_kernel(float* __restrict__ out) {
    extern __shared__ float shk[];   // 2048 rows x 16 floats, swizzled chunks
    int b    = blockIdx.x >> 5;
    int tile = blockIdx.x & 31;

    const float* fkb = g_fk + (size_t)b * Sn * OUTC;
    const float* fqb = g_fq + (size_t)b * Sn * OUTC;

    // stage fk[b] with 16B-chunk swizzle (conflict-free STS and LDS)
    const float4* fkb4 = reinterpret_cast<const float4*>(fkb);
    for (int i = threadIdx.x; i < Sn * 4; i += blockDim.x) {
        int t = i >> 2, j = i & 3;
        float4 v = fkb4[i];
        int jj = j ^ ((t >> 1) & 3);
        *reinterpret_cast<float4*>(&shk[t * 16 + jj * 4]) = v;
    }
    __syncthreads();

    int w    = threadIdx.x >> 5;      // 0..15
    int lane = threadIdx.x & 31;
    int s0   = tile * 64 + w * 4;

    // 4 q rows, channel-pair packed, prescaled by SCALE (8 ull per row)
    ull q2[4][8];
    {
        const ull S2 = pack2(F_SCALE, F_SCALE);
#pragma unroll
        for (int r = 0; r < 4; r++) {
            const float4* qr = reinterpret_cast<const float4*>(
                fqb + (size_t)(s0 + r) * OUTC);
#pragma unroll
            for (int j = 0; j < 4; j++) {
                float4 v = __ldg(&qr[j]);
                ull p0 = pack2(v.x, v.y), p1 = pack2(v.z, v.w);
                MUL2(q2[r][2 * j + 0], p0, S2);
                MUL2(q2[r][2 * j + 1], p1, S2);
            }
        }
    }

    const ull C2 = pack2(-F_SCALE, 0.0f);
    float sum[4] = {0.f, 0.f, 0.f, 0.f};

    for (int t = lane; t < Sn; t += 32) {
        const float* kb = &shk[t * 16];
        int sw = (t >> 1) & 3;
        // 4 LDS.128 -> 8 f32x2 channel pairs, no repacking
        ull k2[8];
#pragma unroll
        for (int j = 0; j < 4; j++) {
            float4 k = *reinterpret_cast<const float4*>(&kb[((j ^ sw) << 2)]);
            k2[2 * j + 0] = pack2(k.x, k.y);
            k2[2 * j + 1] = pack2(k.z, k.w);
        }
        ull d0 = C2, d1 = C2, d2 = C2, d3 = C2;
#pragma unroll
        for (int c = 0; c < 8; c++) {
            FMA2(d0, q2[0][c], k2[c]);
            FMA2(d1, q2[1][c], k2[c]);
            FMA2(d2, q2[2][c], k2[c]);
            FMA2(d3, q2[3][c], k2[c]);
        }
        float lo, hi;
        unpack2(d0, lo, hi); sum[0] += ex2f(lo + hi);
        unpack2(d1, lo, hi); sum[1] += ex2f(lo + hi);
        unpack2(d2, lo, hi); sum[2] += ex2f(lo + hi);
        unpack2(d3, lo, hi); sum[3] += ex2f(lo + hi);
    }

#pragma unroll
    for (int r = 0; r < 4; r++) {
#pragma unroll
        for (int o = 16; o > 0; o >>= 1)
            sum[r] += __shfl_xor_sync(0xFFFFFFFFu, sum[r], o);
    }

    if (lane == 0) {
        float acc = 0.f;
#pragma unroll
        for (int r = 0; r < 4; r++) {
            int s = s0 + r;
            int sw = (s >> 1) & 3;
            const float* ks = &shk[s * 16];
            float d = -F_SCALE;          // x_ss = q'.k_s - SCALE
#pragma unroll
            for (int c = 0; c < 16; c++) {
                int j = c >> 2;
                float kv = ks[((j ^ sw) << 2) + (c & 3)];
                float qlo, qhi;
                unpack2(q2[r][c >> 1], qlo, qhi);
                d = fmaf((c & 1) ? qhi : qlo, kv, d);
            }
            // exact: loss_row = ln2 * (log2(sum) - x_ss); the SCALE shift
            // cancels between the two terms. (No extra +1/tau!)
            acc += F_LN2 * (lg2f(sum[r]) - d);
        }
        atomicAdd(out, acc * (1.0f / (float)(Bn * Sn)));
    }
}

// ---------------------------------------------------------------------------
extern "C" void kernel_launch(void* const* d_in, const int* in_sizes, int n_in,
                              void* d_out, int out_size) {
    const float* f_q  = (const float*)d_in[0];
    const float* f_k  = (const float*)d_in[1];
    const float* W0   = (const float*)d_in[2];
    const float* b0   = (const float*)d_in[3];
    const float* W1   = (const float*)d_in[4];
    const float* b1   = (const float*)d_in[5];
    const int*   c_id = (const int*)d_in[6];
    const int*   n_id = (const int*)d_in[7];
    float* out = (float*)d_out;

    int mlp_smem = (128 * XPAD + 64 * 64 + 64 * 16 + 64 + 16) * (int)sizeof(float);
    cudaFuncSetAttribute(mlp_kernel,
                         cudaFuncAttributeMaxDynamicSharedMemorySize, mlp_smem);
    cudaFuncSetAttribute(loss_kernel,
                         cudaFuncAttributeMaxDynamicSharedMemorySize,
                         Sn * OUTC * (int)sizeof(float));

    gather_diff_kernel<<<2 * Bn * Cn, 256>>>(f_q, f_k, c_id, n_id, out);
    mlp_kernel<<<16 * 16, 128, mlp_smem>>>(W0, b0, W1, b1);
    loss_kernel<<<Bn * 32, 512, Sn * OUTC * (int)sizeof(float)>>>(out);
}